// round 15
// baseline (speedup 1.0000x reference)
#include <cuda_runtime.h>
#include <cuda_fp16.h>
#include <cstdint>

// Problem constants (N = 262144, D = 64, K = 512)
#define NROWS 262144
#define DIM   64
#define KCB   512

#define THREADS 256
#define TILE_M  128
#define RTILES  (NROWS / TILE_M)     // 2048 row tiles; grid = (2048, 2)
#define KHALF   256

#define RSCALE     2048.0f           // 2^11: lifts fp16 residuals out of subnormals
#define RSCALE_INV 4.8828125e-4f     // exact 2^-11

// smem layout (bytes) — ~98 KB so TWO CTAs fit per SM
#define SM_BH   0                    // 256 x 128B B-hi (this K-half)
#define SM_BL   32768                // 256 x 128B B-lo
#define SM_AH   65536                // 128 x 128B A-hi
#define SM_AL   81920                // 128 x 128B A-lo
#define SM_W2   98304                // 256 f32 (this K-half)
#define SM_X2   99328                // 128 f32
#define SM_RED  99840                // 8 doubles
#define SMEM_BYTES 99968

typedef unsigned long long ull;

// Scratch (static device memory — allocation-free)
__device__ uint8_t  g_wimg[131072];  // swizzled fp16 W image: hi @0, lo(scaled) @65536
__device__ float    g_w2[KCB];
__device__ ull      g_best[NROWS];   // holds ~key; zero-init OK for atomicMax
__device__ unsigned g_tick[RTILES];  // per-rowtile pair ticket
__device__ double   g_partials[RTILES];
__device__ unsigned g_ticket;        // loss ticket; reset by last CTA

// ---- helpers ----
__device__ __forceinline__ uint32_t swz(uint32_t r, uint32_t cbyte) {
    return r * 128u + (cbyte ^ ((r & 7u) << 4));
}
__device__ __forceinline__ uint32_t smem_u32(const void* p) {
    uint32_t a;
    asm("{ .reg .u64 t; cvta.to.shared.u64 t, %1; cvt.u32.u64 %0, t; }"
        : "=r"(a) : "l"(p));
    return a;
}
__device__ __forceinline__ void ldsm4(uint32_t r[4], uint32_t addr) {
    asm volatile("ldmatrix.sync.aligned.m8n8.x4.shared.b16 {%0,%1,%2,%3}, [%4];"
                 : "=r"(r[0]), "=r"(r[1]), "=r"(r[2]), "=r"(r[3]) : "r"(addr));
}
__device__ __forceinline__ void mma16816(float& d0, float& d1, float& d2, float& d3,
                                         const uint32_t* a, uint32_t b0, uint32_t b1) {
    asm volatile("mma.sync.aligned.m16n8k16.row.col.f32.f16.f16.f32 "
                 "{%0,%1,%2,%3}, {%4,%5,%6,%7}, {%8,%9}, {%0,%1,%2,%3};"
                 : "+f"(d0), "+f"(d1), "+f"(d2), "+f"(d3)
                 : "r"(a[0]), "r"(a[1]), "r"(a[2]), "r"(a[3]), "r"(b0), "r"(b1));
}
__device__ __forceinline__ ull umin64(ull a, ull b) { return a < b ? a : b; }

// Convert one fp32 row: stage in regs, ssq in exact sequential order, then
// stores with a per-row j-rotation to kill the 4-way STS bank conflict.
__device__ __forceinline__ float conv_row_f16_rot(const float4* __restrict__ s4,
                                                  char* hi, char* lo, int row,
                                                  int rot) {
    float4 v[16];
    #pragma unroll
    for (int j = 0; j < 16; j++) v[j] = s4[j];

    float ssq = 0.0f;
    #pragma unroll
    for (int j = 0; j < 16; j++) {     // sequential: matches jnp.sum(x*x, axis=1)
        ssq = __fadd_rn(ssq, __fmul_rn(v[j].x, v[j].x));
        ssq = __fadd_rn(ssq, __fmul_rn(v[j].y, v[j].y));
        ssq = __fadd_rn(ssq, __fmul_rn(v[j].z, v[j].z));
        ssq = __fadd_rn(ssq, __fmul_rn(v[j].w, v[j].w));
    }

    #pragma unroll
    for (int jj = 0; jj < 16; jj++) {
        int j = (jj + rot) & 15;       // rotated store order (layout unchanged)
        __half h0 = __float2half_rn(v[j].x), h1 = __float2half_rn(v[j].y);
        __half h2 = __float2half_rn(v[j].z), h3 = __float2half_rn(v[j].w);
        __half l0 = __float2half_rn(__fmul_rn(__fsub_rn(v[j].x, __half2float(h0)), RSCALE));
        __half l1 = __float2half_rn(__fmul_rn(__fsub_rn(v[j].y, __half2float(h1)), RSCALE));
        __half l2 = __float2half_rn(__fmul_rn(__fsub_rn(v[j].z, __half2float(h2)), RSCALE));
        __half l3 = __float2half_rn(__fmul_rn(__fsub_rn(v[j].w, __half2float(h3)), RSCALE));

        uint32_t hA = (uint32_t)__half_as_ushort(h0) | ((uint32_t)__half_as_ushort(h1) << 16);
        uint32_t hB = (uint32_t)__half_as_ushort(h2) | ((uint32_t)__half_as_ushort(h3) << 16);
        uint32_t lA = (uint32_t)__half_as_ushort(l0) | ((uint32_t)__half_as_ushort(l1) << 16);
        uint32_t lB = (uint32_t)__half_as_ushort(l2) | ((uint32_t)__half_as_ushort(l3) << 16);

        uint32_t off = swz((uint32_t)row, (uint32_t)(j * 8));
        *(uint2*)(hi + off) = make_uint2(hA, hB);
        *(uint2*)(lo + off) = make_uint2(lA, lB);
    }
    return ssq;
}

// ============================ Prep: W -> fp16 image + w2 ============================
__global__ __launch_bounds__(128)
void vq_prep(const float* __restrict__ W) {
    const int k = blockIdx.x * 128 + threadIdx.x;
    g_w2[k] = conv_row_f16_rot((const float4*)(W + (size_t)k * DIM),
                               (char*)g_wimg, (char*)g_wimg + 65536, k,
                               ((k >> 3) & 3) * 4);
}

// ============================ Main (split-K, 2 CTAs/SM) ============================
__global__ __launch_bounds__(THREADS, 2)
void vq_main(const float* __restrict__ enc,
             const float* __restrict__ W,
             float* __restrict__ out) {
    extern __shared__ char sm[];
    const uint32_t sb = smem_u32(sm);
    float* sx2 = (float*)(sm + SM_X2);

    const int tid  = threadIdx.x;
    const int wid  = tid >> 5;
    const int lane = tid & 31;
    const int bx   = blockIdx.x;          // row tile
    const int kh   = blockIdx.y;          // K half
    const int rowbase = bx * TILE_M;

    // Phase 0: threads 0-127 convert X rows; 128-255 copy this half's B image
    if (tid < TILE_M) {
        sx2[tid] = conv_row_f16_rot((const float4*)(enc + (size_t)(rowbase + tid) * DIM),
                                    sm + SM_AH, sm + SM_AL, tid,
                                    ((tid >> 3) & 3) * 4);
    } else {
        const int i = tid - TILE_M;        // 0..127
        const uint4* srcH = (const uint4*)(g_wimg + (size_t)kh * 32768);
        const uint4* srcL = (const uint4*)(g_wimg + 65536 + (size_t)kh * 32768);
        uint4* dstH = (uint4*)(sm + SM_BH);
        uint4* dstL = (uint4*)(sm + SM_BL);
        #pragma unroll
        for (int j = 0; j < 16; j++) {
            dstH[i + j * 128] = srcH[i + j * 128];
            dstL[i + j * 128] = srcL[i + j * 128];
        }
        ((float*)(sm + SM_W2))[i]       = g_w2[kh * KHALF + i];
        ((float*)(sm + SM_W2))[i + 128] = g_w2[kh * KHALF + i + 128];
    }
    __syncthreads();

    // Phase 1: warp owns rows wid*16..+16 (A resident), streams 32 B tiles
    const int r0 = wid * 16;

    uint32_t ah[4][4], al[4][4];
    {
        const uint32_t cc = (uint32_t)((lane >> 4) << 4);
        const uint32_t rr = (uint32_t)(r0 + (lane & 15));
        #pragma unroll
        for (int ks = 0; ks < 4; ks++) {
            uint32_t off = swz(rr, (uint32_t)(ks * 32) + cc);
            ldsm4(ah[ks], sb + SM_AH + off);
            ldsm4(al[ks], sb + SM_AL + off);
        }
    }
    const float x2A = sx2[r0 + (lane >> 2)];
    const float x2B = sx2[r0 + (lane >> 2) + 8];
    const int   cix = 2 * (lane & 3);

    ull bestA = ~0ull, bestB = ~0ull;

    // B addressing: local row = t*8 + bn; swizzle XOR loop-invariant
    const uint32_t bn = (uint32_t)(lane & 7);
    const uint32_t bc = (uint32_t)((lane >> 3) << 4);
    const uint32_t x0 = bc ^ (bn << 4);
    const uint32_t dlt = ((64u + bc) ^ (bn << 4)) - x0;
    uint32_t pbh = sb + SM_BH + bn * 128u + x0;
    uint32_t pbl = sb + SM_BL + bn * 128u + x0;
    const float* pw2 = (const float*)(sm + SM_W2) + cix;
    const int cbase = kh * KHALF + cix;

    #pragma unroll 2
    for (int t = 0; t < 32; t += 2) {
        uint32_t bhu[8], blu[8], bhv[8], blv[8];
        ldsm4(bhu,     pbh);
        ldsm4(bhu + 4, pbh + dlt);
        ldsm4(bhv,     pbh + 1024u);
        ldsm4(bhv + 4, pbh + 1024u + dlt);
        ldsm4(blu,     pbl);
        ldsm4(blu + 4, pbl + dlt);
        ldsm4(blv,     pbl + 1024u);
        ldsm4(blv + 4, pbl + 1024u + dlt);
        pbh += 2048u;
        pbl += 2048u;

        float uh0 = 0.f, uh1 = 0.f, uh2 = 0.f, uh3 = 0.f;
        float vh0 = 0.f, vh1 = 0.f, vh2 = 0.f, vh3 = 0.f;
        float uc0 = 0.f, uc1 = 0.f, uc2 = 0.f, uc3 = 0.f;
        float vc0 = 0.f, vc1 = 0.f, vc2 = 0.f, vc3 = 0.f;
        #pragma unroll
        for (int ks = 0; ks < 4; ks++) {   // hh: xh . wh
            mma16816(uh0, uh1, uh2, uh3, ah[ks], bhu[2 * ks], bhu[2 * ks + 1]);
            mma16816(vh0, vh1, vh2, vh3, ah[ks], bhv[2 * ks], bhv[2 * ks + 1]);
        }
        #pragma unroll
        for (int ks = 0; ks < 4; ks++) {   // hl: xh . wl'  (scale 2^11)
            mma16816(uc0, uc1, uc2, uc3, ah[ks], blu[2 * ks], blu[2 * ks + 1]);
            mma16816(vc0, vc1, vc2, vc3, ah[ks], blv[2 * ks], blv[2 * ks + 1]);
        }
        #pragma unroll
        for (int ks = 0; ks < 4; ks++) {   // lh: xl' . wh  (scale 2^11)
            mma16816(uc0, uc1, uc2, uc3, al[ks], bhu[2 * ks], bhu[2 * ks + 1]);
            mma16816(vc0, vc1, vc2, vc3, al[ks], bhv[2 * ks], bhv[2 * ks + 1]);
        }

        // Epilogue tile u
        {
            const int c0 = cbase + t * 8;
            float2 w2v = *(const float2*)pw2;
            float dot0 = __fmaf_rn(uc0, RSCALE_INV, uh0);
            float dot1 = __fmaf_rn(uc1, RSCALE_INV, uh1);
            float dot2 = __fmaf_rn(uc2, RSCALE_INV, uh2);
            float dot3 = __fmaf_rn(uc3, RSCALE_INV, uh3);
            // d = fl(fl(x2 - fl(2*dot)) + w2)  — exact reference op order
            float d0 = __fadd_rn(__fsub_rn(x2A, __fadd_rn(dot0, dot0)), w2v.x);
            float d1 = __fadd_rn(__fsub_rn(x2A, __fadd_rn(dot1, dot1)), w2v.y);
            float d2 = __fadd_rn(__fsub_rn(x2B, __fadd_rn(dot2, dot2)), w2v.x);
            float d3 = __fadd_rn(__fsub_rn(x2B, __fadd_rn(dot3, dot3)), w2v.y);
            bestA = umin64(bestA, ((ull)__float_as_uint(d0) << 32) | (unsigned)c0);
            bestA = umin64(bestA, ((ull)__float_as_uint(d1) << 32) | (unsigned)(c0 + 1));
            bestB = umin64(bestB, ((ull)__float_as_uint(d2) << 32) | (unsigned)c0);
            bestB = umin64(bestB, ((ull)__float_as_uint(d3) << 32) | (unsigned)(c0 + 1));
        }
        // Epilogue tile v
        {
            const int c0 = cbase + (t + 1) * 8;
            float2 w2v = *(const float2*)(pw2 + 8);
            float dot0 = __fmaf_rn(vc0, RSCALE_INV, vh0);
            float dot1 = __fmaf_rn(vc1, RSCALE_INV, vh1);
            float dot2 = __fmaf_rn(vc2, RSCALE_INV, vh2);
            float dot3 = __fmaf_rn(vc3, RSCALE_INV, vh3);
            float d0 = __fadd_rn(__fsub_rn(x2A, __fadd_rn(dot0, dot0)), w2v.x);
            float d1 = __fadd_rn(__fsub_rn(x2A, __fadd_rn(dot1, dot1)), w2v.y);
            float d2 = __fadd_rn(__fsub_rn(x2B, __fadd_rn(dot2, dot2)), w2v.x);
            float d3 = __fadd_rn(__fsub_rn(x2B, __fadd_rn(dot3, dot3)), w2v.y);
            bestA = umin64(bestA, ((ull)__float_as_uint(d0) << 32) | (unsigned)c0);
            bestA = umin64(bestA, ((ull)__float_as_uint(d1) << 32) | (unsigned)(c0 + 1));
            bestB = umin64(bestB, ((ull)__float_as_uint(d2) << 32) | (unsigned)c0);
            bestB = umin64(bestB, ((ull)__float_as_uint(d3) << 32) | (unsigned)(c0 + 1));
        }
        pw2 += 16;
    }

    // Cross-lane argmin; publish inverted key so zero-init atomicMax works
    bestA = umin64(bestA, __shfl_xor_sync(0xFFFFFFFFu, bestA, 1));
    bestA = umin64(bestA, __shfl_xor_sync(0xFFFFFFFFu, bestA, 2));
    bestB = umin64(bestB, __shfl_xor_sync(0xFFFFFFFFu, bestB, 1));
    bestB = umin64(bestB, __shfl_xor_sync(0xFFFFFFFFu, bestB, 2));
    if ((lane & 3) == 0) {
        atomicMax(&g_best[rowbase + r0 + (lane >> 2)],     ~bestA);
        atomicMax(&g_best[rowbase + r0 + (lane >> 2) + 8], ~bestB);
    }
    __threadfence();
    __syncthreads();

    // Pair ticket: second-arriving CTA does the output phase for this tile
    __shared__ bool s_out;
    if (tid == 0) s_out = (atomicAdd(&g_tick[bx], 1u) == 1u);
    __syncthreads();
    if (!s_out) return;
    __threadfence();   // make the other CTA's atomicMax results visible

    // Output phase: 2 threads per row; combine via inverted-key max
    const int row  = tid >> 1;
    const int half = tid & 1;
    const ull key  = ~g_best[rowbase + row];
    const int bi   = (int)(unsigned)(key & 0xFFFFFFFFull);
    __syncthreads();                       // all reads done before reset
    if (!half) g_best[rowbase + row] = 0;  // reset for next graph replay
    if (tid == 0) g_tick[bx] = 0;
    if (!half) out[rowbase + row] = (float)bi;

    const float4* xg = (const float4*)(enc + (size_t)(rowbase + row) * DIM);
    const float4* qg = (const float4*)(W + (size_t)bi * DIM);
    float4* o = (float4*)(out + NROWS + (size_t)(rowbase + row) * DIM);

    float s0 = 0.f, s1 = 0.f, s2 = 0.f, s3 = 0.f;
    const int j0 = half * 8;
    #pragma unroll
    for (int s = 0; s < 8; s++) {
        int j = j0 + s;
        float4 x = xg[j];
        float4 q = __ldg(&qg[j]);
        float d0 = __fsub_rn(q.x, x.x);
        float d1 = __fsub_rn(q.y, x.y);
        float d2 = __fsub_rn(q.z, x.z);
        float d3 = __fsub_rn(q.w, x.w);
        float4 rr;
        rr.x = __fadd_rn(x.x, d0);   // straight-through: fl(x + fl(q - x))
        rr.y = __fadd_rn(x.y, d1);
        rr.z = __fadd_rn(x.z, d2);
        rr.w = __fadd_rn(x.w, d3);
        o[j] = rr;
        s0 = __fmaf_rn(d0, d0, s0);
        s1 = __fmaf_rn(d1, d1, s1);
        s2 = __fmaf_rn(d2, d2, s2);
        s3 = __fmaf_rn(d3, d3, s3);
    }
    double lsum = (double)((s0 + s1) + (s2 + s3));

    // Loss reduction: warp -> CTA -> global ticket over RTILES output-CTAs
    #pragma unroll
    for (int off = 16; off > 0; off >>= 1)
        lsum += __shfl_xor_sync(0xFFFFFFFFu, lsum, off);

    double* swarp = (double*)(sm + SM_RED);
    __shared__ bool s_last;
    if (lane == 0) swarp[wid] = lsum;
    __syncthreads();

    if (tid == 0) {
        double bsum = 0.0;
        #pragma unroll
        for (int w = 0; w < THREADS / 32; w++) bsum += swarp[w];
        g_partials[bx] = bsum;
        __threadfence();
        unsigned old = atomicAdd(&g_ticket, 1u);
        s_last = (old == RTILES - 1);
    }
    __syncthreads();

    if (s_last) {
        double t = 0.0;
        for (int i = tid; i < RTILES; i += THREADS) t += g_partials[i];
        #pragma unroll
        for (int off = 16; off > 0; off >>= 1)
            t += __shfl_xor_sync(0xFFFFFFFFu, t, off);
        if (lane == 0) swarp[wid] = t;
        __syncthreads();
        if (tid == 0) {
            double tot = 0.0;
            #pragma unroll
            for (int w = 0; w < THREADS / 32; w++) tot += swarp[w];
            float m2 = (float)(tot / (double)((size_t)NROWS * DIM));
            // vq_loss = fl(fl(mean*0.25) + mean)
            out[(size_t)NROWS * (DIM + 1)] = __fadd_rn(__fmul_rn(m2, 0.25f), m2);
            g_ticket = 0;   // deterministic across graph replays
        }
    }
}

extern "C" void kernel_launch(void* const* d_in, const int* in_sizes, int n_in,
                              void* d_out, int out_size) {
    const float* enc = (const float*)d_in[0];   // [N, 64] fp32
    const float* W   = (const float*)d_in[1];   // [512, 64] fp32
    float* out = (float*)d_out;                 // [N | N*64 | 1] fp32

    cudaFuncSetAttribute(vq_main,
                         cudaFuncAttributeMaxDynamicSharedMemorySize, SMEM_BYTES);

    vq_prep<<<KCB / 128, 128>>>(W);
    dim3 grid(RTILES, 2);
    vq_main<<<grid, THREADS, SMEM_BYTES>>>(enc, W, out);
}

// round 16
// speedup vs baseline: 1.2706x; 1.2706x over previous
#include <cuda_runtime.h>
#include <cuda_fp16.h>
#include <cstdint>

// Problem constants (N = 262144, D = 64, K = 512)
#define NROWS 262144
#define DIM   64
#define KCB   512

#define THREADS 512
#define TILE_M  256
#define BLOCKS  (NROWS / TILE_M)     // 1024

#define RSCALE     2048.0f           // 2^11: lifts fp16 residuals out of subnormals
#define RSCALE_INV 4.8828125e-4f     // exact 2^-11

// smem layout (bytes)
#define SM_BH   0                    // 512 x 128B
#define SM_BL   65536                // 512 x 128B
#define SM_AH   131072               // 256 x 128B
#define SM_AL   163840               // 256 x 128B
#define SM_W2   196608               // 512 f32
#define SM_X2   198656               // 256 f32
#define SM_RED  199680               // 16 doubles
#define SMEM_BYTES 199808

typedef unsigned long long ull;

// Scratch (static device memory — allocation-free)
__device__ uint8_t  g_wimg[131072];  // swizzled fp16 W image: hi @0, lo(scaled) @65536
__device__ float    g_w2[KCB];
__device__ double   g_partials[BLOCKS];
__device__ unsigned g_ticket;        // zero-init; last CTA resets to 0

// ---- helpers ----
__device__ __forceinline__ uint32_t swz(uint32_t r, uint32_t cbyte) {
    // 128B rows, 8-row XOR swizzle: conflict-free for ldmatrix
    return r * 128u + (cbyte ^ ((r & 7u) << 4));
}
__device__ __forceinline__ uint32_t smem_u32(const void* p) {
    uint32_t a;
    asm("{ .reg .u64 t; cvta.to.shared.u64 t, %1; cvt.u32.u64 %0, t; }"
        : "=r"(a) : "l"(p));
    return a;
}
__device__ __forceinline__ void ldsm4(uint32_t r[4], uint32_t addr) {
    asm volatile("ldmatrix.sync.aligned.m8n8.x4.shared.b16 {%0,%1,%2,%3}, [%4];"
                 : "=r"(r[0]), "=r"(r[1]), "=r"(r[2]), "=r"(r[3]) : "r"(addr));
}
__device__ __forceinline__ void mma16816(float& d0, float& d1, float& d2, float& d3,
                                         const uint32_t* a, uint32_t b0, uint32_t b1) {
    asm volatile("mma.sync.aligned.m16n8k16.row.col.f32.f16.f16.f32 "
                 "{%0,%1,%2,%3}, {%4,%5,%6,%7}, {%8,%9}, {%0,%1,%2,%3};"
                 : "+f"(d0), "+f"(d1), "+f"(d2), "+f"(d3)
                 : "r"(a[0]), "r"(a[1]), "r"(a[2]), "r"(a[3]), "r"(b0), "r"(b1));
}

// Convert one fp32 row: stage in regs, ssq in exact sequential order, then
// stores with a per-row j-rotation to kill the 4-way STS bank conflict.
__device__ __forceinline__ float conv_row_f16_rot(const float4* __restrict__ s4,
                                                  char* hi, char* lo, int row,
                                                  int rot) {
    float4 v[16];
    #pragma unroll
    for (int j = 0; j < 16; j++) v[j] = s4[j];

    float ssq = 0.0f;
    #pragma unroll
    for (int j = 0; j < 16; j++) {     // sequential: matches jnp.sum(x*x, axis=1)
        ssq = __fadd_rn(ssq, __fmul_rn(v[j].x, v[j].x));
        ssq = __fadd_rn(ssq, __fmul_rn(v[j].y, v[j].y));
        ssq = __fadd_rn(ssq, __fmul_rn(v[j].z, v[j].z));
        ssq = __fadd_rn(ssq, __fmul_rn(v[j].w, v[j].w));
    }

    #pragma unroll
    for (int jj = 0; jj < 16; jj++) {
        int j = (jj + rot) & 15;       // rotated store order (layout unchanged)
        __half h0 = __float2half_rn(v[j].x), h1 = __float2half_rn(v[j].y);
        __half h2 = __float2half_rn(v[j].z), h3 = __float2half_rn(v[j].w);
        __half l0 = __float2half_rn(__fmul_rn(__fsub_rn(v[j].x, __half2float(h0)), RSCALE));
        __half l1 = __float2half_rn(__fmul_rn(__fsub_rn(v[j].y, __half2float(h1)), RSCALE));
        __half l2 = __float2half_rn(__fmul_rn(__fsub_rn(v[j].z, __half2float(h2)), RSCALE));
        __half l3 = __float2half_rn(__fmul_rn(__fsub_rn(v[j].w, __half2float(h3)), RSCALE));

        uint32_t hA = (uint32_t)__half_as_ushort(h0) | ((uint32_t)__half_as_ushort(h1) << 16);
        uint32_t hB = (uint32_t)__half_as_ushort(h2) | ((uint32_t)__half_as_ushort(h3) << 16);
        uint32_t lA = (uint32_t)__half_as_ushort(l0) | ((uint32_t)__half_as_ushort(l1) << 16);
        uint32_t lB = (uint32_t)__half_as_ushort(l2) | ((uint32_t)__half_as_ushort(l3) << 16);

        uint32_t off = swz((uint32_t)row, (uint32_t)(j * 8));
        *(uint2*)(hi + off) = make_uint2(hA, hB);
        *(uint2*)(lo + off) = make_uint2(lA, lB);
    }
    return ssq;
}

// ============================ Prep: W -> fp16 image + w2 ============================
__global__ __launch_bounds__(128)
void vq_prep(const float* __restrict__ W) {
    const int k = blockIdx.x * 128 + threadIdx.x;
    g_w2[k] = conv_row_f16_rot((const float4*)(W + (size_t)k * DIM),
                               (char*)g_wimg, (char*)g_wimg + 65536, k,
                               ((k >> 3) & 3) * 4);
}

// ============================ Main (fused) ============================
__global__ __launch_bounds__(THREADS, 1)
void vq_main(const float* __restrict__ enc,
             const float* __restrict__ W,
             float* __restrict__ out) {
    extern __shared__ char sm[];
    const uint32_t sb = smem_u32(sm);
    float* sx2 = (float*)(sm + SM_X2);

    const int tid  = threadIdx.x;
    const int wid  = tid >> 5;
    const int lane = tid & 31;
    const int rowbase = blockIdx.x * TILE_M;

    // Phase 0: threads 0-255 convert one X row each; 256-511 copy W image + w2
    if (tid < 256) {
        sx2[tid] = conv_row_f16_rot((const float4*)(enc + (size_t)(rowbase + tid) * DIM),
                                    sm + SM_AH, sm + SM_AL, tid,
                                    ((tid >> 3) & 3) * 4);
    } else {
        const int i = tid - 256;
        const uint4* src = (const uint4*)g_wimg;
        uint4*       dst = (uint4*)(sm + SM_BH);
        #pragma unroll
        for (int j = 0; j < 32; j++) dst[i + j * 256] = src[i + j * 256];
        ((float*)(sm + SM_W2))[i]       = g_w2[i];
        ((float*)(sm + SM_W2))[i + 256] = g_w2[i + 256];
    }
    __syncthreads();

    // Phase 1: per-warp MMA over 16 rows x 512 cols
    const int r0 = wid * 16;

    // A fragments: 4 k-steps x 4 regs, hi and scaled-lo
    uint32_t ah[4][4], al[4][4];
    {
        const uint32_t cc = (uint32_t)((lane >> 4) << 4);
        const uint32_t rr = (uint32_t)(r0 + (lane & 15));
        #pragma unroll
        for (int ks = 0; ks < 4; ks++) {
            uint32_t off = swz(rr, (uint32_t)(ks * 32) + cc);
            ldsm4(ah[ks], sb + SM_AH + off);
            ldsm4(al[ks], sb + SM_AL + off);
        }
    }

    const float x2A = sx2[r0 + (lane >> 2)];
    const float x2B = sx2[r0 + (lane >> 2) + 8];

    // Running argmin: float distance + int column (strict < = first occurrence)
    float bestdA = __int_as_float(0x7f800000), bestdB = bestdA;
    int   bestcA = 0, bestcB = 0;

    // B address strength reduction: row = t*8 + bn, (row & 7) == bn for all t,
    // so the swizzle XOR is loop-invariant. Bump base by 2048 per t+=2.
    const uint32_t bn = (uint32_t)(lane & 7);
    const uint32_t bc = (uint32_t)((lane >> 3) << 4);
    const uint32_t x0 = bc ^ (bn << 4);
    const uint32_t x1 = (64u + bc) ^ (bn << 4);
    uint32_t pbh = sb + SM_BH + bn * 128u + x0;
    uint32_t pbl = pbh + 65536u;
    const uint32_t dlt = x1 - x0;          // constant offset to the 64B half
    const float* pw2 = (const float*)(sm + SM_W2) + 2 * (lane & 3);
    int cu = 2 * (lane & 3);               // tile-u column for this lane

    #pragma unroll 2
    for (int t = 0; t < 64; t += 2) {
        // B fragments for tiles u, v=u+1 (hi and scaled-lo, 4 k-steps each)
        uint32_t bhu[8], blu[8], bhv[8], blv[8];
        ldsm4(bhu,     pbh);
        ldsm4(bhu + 4, pbh + dlt);
        ldsm4(bhv,     pbh + 1024u);
        ldsm4(bhv + 4, pbh + 1024u + dlt);
        ldsm4(blu,     pbl);
        ldsm4(blu + 4, pbl + dlt);
        ldsm4(blv,     pbl + 1024u);
        ldsm4(blv + 4, pbl + 1024u + dlt);
        pbh += 2048u;
        pbl += 2048u;

        // hh accumulators (scale 1) and cross accumulators (scale 2^-11)
        float uh0 = 0.f, uh1 = 0.f, uh2 = 0.f, uh3 = 0.f;
        float vh0 = 0.f, vh1 = 0.f, vh2 = 0.f, vh3 = 0.f;
        float uc0 = 0.f, uc1 = 0.f, uc2 = 0.f, uc3 = 0.f;
        float vc0 = 0.f, vc1 = 0.f, vc2 = 0.f, vc3 = 0.f;
        #pragma unroll
        for (int ks = 0; ks < 4; ks++) {   // hh: xh . wh
            mma16816(uh0, uh1, uh2, uh3, ah[ks], bhu[2 * ks], bhu[2 * ks + 1]);
            mma16816(vh0, vh1, vh2, vh3, ah[ks], bhv[2 * ks], bhv[2 * ks + 1]);
        }
        #pragma unroll
        for (int ks = 0; ks < 4; ks++) {   // hl: xh . wl'   (scale 2^11)
            mma16816(uc0, uc1, uc2, uc3, ah[ks], blu[2 * ks], blu[2 * ks + 1]);
            mma16816(vc0, vc1, vc2, vc3, ah[ks], blv[2 * ks], blv[2 * ks + 1]);
        }
        #pragma unroll
        for (int ks = 0; ks < 4; ks++) {   // lh: xl' . wh   (scale 2^11)
            mma16816(uc0, uc1, uc2, uc3, al[ks], bhu[2 * ks], bhu[2 * ks + 1]);
            mma16816(vc0, vc1, vc2, vc3, al[ks], bhv[2 * ks], bhv[2 * ks + 1]);
        }

        // Epilogue tile u. fl(2*dot) is exact, so
        // d = fl(fl(x2 - fl(2*dot)) + w2) == fl(fma(dot,-2,x2)) + w2 rounding —
        // bit-identical to the reference op order.
        {
            float2 w2v = *(const float2*)pw2;
            float dot0 = __fmaf_rn(uc0, RSCALE_INV, uh0);
            float dot1 = __fmaf_rn(uc1, RSCALE_INV, uh1);
            float dot2 = __fmaf_rn(uc2, RSCALE_INV, uh2);
            float dot3 = __fmaf_rn(uc3, RSCALE_INV, uh3);
            float d0 = __fadd_rn(__fmaf_rn(dot0, -2.0f, x2A), w2v.x);
            float d1 = __fadd_rn(__fmaf_rn(dot1, -2.0f, x2A), w2v.y);
            float d2 = __fadd_rn(__fmaf_rn(dot2, -2.0f, x2B), w2v.x);
            float d3 = __fadd_rn(__fmaf_rn(dot3, -2.0f, x2B), w2v.y);
            bool  p  = d1 < d0;            // strict: smaller col wins ties
            float dm = p ? d1 : d0;
            int   cm = cu + (p ? 1 : 0);
            if (dm < bestdA) { bestdA = dm; bestcA = cm; }
            bool  q  = d3 < d2;
            float dn = q ? d3 : d2;
            int   cn = cu + (q ? 1 : 0);
            if (dn < bestdB) { bestdB = dn; bestcB = cn; }
        }
        // Epilogue tile v
        {
            float2 w2v = *(const float2*)(pw2 + 8);
            float dot0 = __fmaf_rn(vc0, RSCALE_INV, vh0);
            float dot1 = __fmaf_rn(vc1, RSCALE_INV, vh1);
            float dot2 = __fmaf_rn(vc2, RSCALE_INV, vh2);
            float dot3 = __fmaf_rn(vc3, RSCALE_INV, vh3);
            float d0 = __fadd_rn(__fmaf_rn(dot0, -2.0f, x2A), w2v.x);
            float d1 = __fadd_rn(__fmaf_rn(dot1, -2.0f, x2A), w2v.y);
            float d2 = __fadd_rn(__fmaf_rn(dot2, -2.0f, x2B), w2v.x);
            float d3 = __fadd_rn(__fmaf_rn(dot3, -2.0f, x2B), w2v.y);
            bool  p  = d1 < d0;
            float dm = p ? d1 : d0;
            int   cm = cu + 8 + (p ? 1 : 0);
            if (dm < bestdA) { bestdA = dm; bestcA = cm; }
            bool  q  = d3 < d2;
            float dn = q ? d3 : d2;
            int   cn = cu + 8 + (q ? 1 : 0);
            if (dn < bestdB) { bestdB = dn; bestcB = cn; }
        }
        pw2 += 16;
        cu  += 16;
    }

    // Cross-lane argmin over the 4 lanes sharing each row.
    // Tie-break: smaller distance first, then smaller column (first occurrence).
    #pragma unroll
    for (int off = 1; off <= 2; off <<= 1) {
        float odA = __shfl_xor_sync(0xFFFFFFFFu, bestdA, off);
        int   ocA = __shfl_xor_sync(0xFFFFFFFFu, bestcA, off);
        if (odA < bestdA || (odA == bestdA && ocA < bestcA)) { bestdA = odA; bestcA = ocA; }
        float odB = __shfl_xor_sync(0xFFFFFFFFu, bestdB, off);
        int   ocB = __shfl_xor_sync(0xFFFFFFFFu, bestcB, off);
        if (odB < bestdB || (odB == bestdB && ocB < bestcB)) { bestdB = odB; bestcB = ocB; }
    }

    const int biA = bestcA;
    const int biB = bestcB;
    const int rA  = rowbase + r0 + (lane >> 2);
    const int rB  = rA + 8;

    if ((lane & 3) == 0) {
        out[rA] = (float)biA;
        out[rB] = (float)biB;
    }

    // Fused gather + straight-through + loss; 4 lanes split a row into 4 chunks
    float s0 = 0.f, s1 = 0.f, s2 = 0.f, s3 = 0.f;
    const int j0 = (lane & 3) * 4;
    #pragma unroll
    for (int r = 0; r < 2; r++) {
        const int row = r ? rB : rA;
        const int bi  = r ? biB : biA;
        const float4* xg = (const float4*)(enc + (size_t)row * DIM);
        const float4* qg = (const float4*)(W + (size_t)bi * DIM);
        float4* o = (float4*)(out + NROWS + (size_t)row * DIM);
        #pragma unroll
        for (int s = 0; s < 4; s++) {
            int j = j0 + s;
            float4 x = xg[j];
            float4 q = __ldg(&qg[j]);
            float d0 = __fsub_rn(q.x, x.x);
            float d1 = __fsub_rn(q.y, x.y);
            float d2 = __fsub_rn(q.z, x.z);
            float d3 = __fsub_rn(q.w, x.w);
            float4 rr;
            rr.x = __fadd_rn(x.x, d0);   // straight-through: fl(x + fl(q - x))
            rr.y = __fadd_rn(x.y, d1);
            rr.z = __fadd_rn(x.z, d2);
            rr.w = __fadd_rn(x.w, d3);
            o[j] = rr;
            s0 = __fmaf_rn(d0, d0, s0);
            s1 = __fmaf_rn(d1, d1, s1);
            s2 = __fmaf_rn(d2, d2, s2);
            s3 = __fmaf_rn(d3, d3, s3);
        }
    }
    double lsum = (double)((s0 + s1) + (s2 + s3));

    // Loss reduction: warp -> CTA -> global ticket
    #pragma unroll
    for (int off = 16; off > 0; off >>= 1)
        lsum += __shfl_xor_sync(0xFFFFFFFFu, lsum, off);

    double* swarp = (double*)(sm + SM_RED);
    __shared__ bool s_last;
    if (lane == 0) swarp[wid] = lsum;
    __syncthreads();

    if (tid == 0) {
        double bsum = 0.0;
        #pragma unroll
        for (int w = 0; w < THREADS / 32; w++) bsum += swarp[w];
        g_partials[blockIdx.x] = bsum;
        __threadfence();
        unsigned old = atomicAdd(&g_ticket, 1u);
        s_last = (old == BLOCKS - 1);
    }
    __syncthreads();

    if (s_last) {
        double t = 0.0;
        for (int i = tid; i < BLOCKS; i += THREADS) t += g_partials[i];
        #pragma unroll
        for (int off = 16; off > 0; off >>= 1)
            t += __shfl_xor_sync(0xFFFFFFFFu, t, off);
        if (lane == 0) swarp[wid] = t;
        __syncthreads();
        if (tid == 0) {
            double tot = 0.0;
            #pragma unroll
            for (int w = 0; w < THREADS / 32; w++) tot += swarp[w];
            float m2 = (float)(tot / (double)((size_t)NROWS * DIM));
            // vq_loss = fl(fl(mean*0.25) + mean)
            out[(size_t)NROWS * (DIM + 1)] = __fadd_rn(__fmul_rn(m2, 0.25f), m2);
            g_ticket = 0;   // deterministic across graph replays
        }
    }
}

extern "C" void kernel_launch(void* const* d_in, const int* in_sizes, int n_in,
                              void* d_out, int out_size) {
    const float* enc = (const float*)d_in[0];   // [N, 64] fp32
    const float* W   = (const float*)d_in[1];   // [512, 64] fp32
    float* out = (float*)d_out;                 // [N | N*64 | 1] fp32

    cudaFuncSetAttribute(vq_main,
                         cudaFuncAttributeMaxDynamicSharedMemorySize, SMEM_BYTES);

    vq_prep<<<KCB / 128, 128>>>(W);
    vq_main<<<BLOCKS, THREADS, SMEM_BYTES>>>(enc, W, out);
}